// round 3
// baseline (speedup 1.0000x reference)
#include <cuda_runtime.h>
#include <math.h>
#include <cstdint>

#define BLOCK 64
#define NSH 81   // sum(2l+1), l=0..8
#define TILE_BYTES (BLOCK * NSH * 4)   // 20736, multiple of 16

// Real spherical harmonics (e3nn SphericalHarmonicsAlphaBeta, l=0..8, mul=1).
// out[n, l*l + l + m] = P̄_{l,|m|}(cos b) * sin(b)^|m| * A_m(a)
//   A_m = 1 (m=0), sqrt(2)*cos(m a) (m>0), sqrt(2)*sin(|m| a) (m<0)
// P̄ via stable fully-normalized ALF recurrences (no Condon-Shortley phase).
// Writeback: one cp.async.bulk (SMEM->GMEM) per CTA — no LDS/STG round trip.
__global__ __launch_bounds__(BLOCK)
void sh_ab_kernel(const float* __restrict__ alpha,
                  const float* __restrict__ beta,
                  float* __restrict__ out, int n)
{
    __shared__ __align__(128) float sh[BLOCK * NSH];   // 20736 B

    const int tid = threadIdx.x;
    const int point = blockIdx.x * BLOCK + tid;

    float a = 0.f, b = 0.f;
    if (point < n) { a = alpha[point]; b = beta[point]; }

    float sa, ca, sb, cb;
    __sincosf(a, &sa, &ca);
    __sincosf(b, &sb, &cb);
    const float z = cb;   // polynomial variable
    const float y = sb;   // sin(beta) >= 0 on [0, pi]

    // cos(m a), sin(m a) for m=0..8 via Chebyshev recurrence
    float cm[9], sn[9];
    cm[0] = 1.f; sn[0] = 0.f;
    cm[1] = ca;  sn[1] = sa;
    const float t2 = 2.f * ca;
#pragma unroll
    for (int m = 2; m <= 8; ++m) {
        cm[m] = t2 * cm[m-1] - cm[m-2];
        sn[m] = t2 * sn[m-1] - sn[m-2];
    }

    const float SQ2 = 1.41421356237309515f;
    float* row = &sh[tid * NSH];

    // m-major sweep: tiny live register set per column
    float pmm = 0.28209479177387814f;   // P̄_00 = sqrt(1/4pi)
#pragma unroll
    for (int m = 0; m <= 8; ++m) {
        if (m > 0)
            pmm *= sqrtf((2.f*m + 1.f) / (2.f*m)) * y;   // sectoral step

        const float Ac = (m == 0) ? 1.f : SQ2 * cm[m];
        const float As = SQ2 * sn[m];

        // l = m
        float plm2 = pmm;
        {
            const int l = m;
            row[l*l + l + m] = plm2 * Ac;
            if (m > 0) row[l*l + l - m] = plm2 * As;
        }
        if (m < 8) {
            // l = m+1
            float plm1 = sqrtf(2.f*m + 3.f) * z * pmm;
            {
                const int l = m + 1;
                row[l*l + l + m] = plm1 * Ac;
                if (m > 0) row[l*l + l - m] = plm1 * As;
            }
            // l = m+2 .. 8
#pragma unroll
            for (int l = m + 2; l <= 8; ++l) {
                const float al = sqrtf((4.f*l*l - 1.f) / (float)(l*l - m*m));
                const float bl = sqrtf((float)((l-1)*(l-1) - m*m) /
                                       (4.f*(l-1)*(l-1) - 1.f));
                const float pl = al * (z * plm1 - bl * plm2);
                row[l*l + l + m] = pl * Ac;
                if (m > 0) row[l*l + l - m] = pl * As;
                plm2 = plm1; plm1 = pl;
            }
        }
    }

    __syncthreads();

    const long long base = (long long)blockIdx.x * (BLOCK * NSH);
    const int remaining = n - blockIdx.x * BLOCK;
    if (remaining >= BLOCK) {
        // Single bulk async store of the whole contiguous tile
        if (tid == 0) {
            asm volatile("fence.proxy.async.shared::cta;" ::: "memory");
            uint32_t s_addr;
            asm("{ .reg .u64 t; cvta.to.shared.u64 t, %1; cvt.u32.u64 %0, t; }"
                : "=r"(s_addr) : "l"(sh));
            asm volatile(
                "cp.async.bulk.global.shared::cta.bulk_group [%0], [%1], %2;"
                :: "l"(out + base), "r"(s_addr), "n"(TILE_BYTES)
                : "memory");
            asm volatile("cp.async.bulk.commit_group;" ::: "memory");
            asm volatile("cp.async.bulk.wait_group.read 0;" ::: "memory");
        }
    } else {
        // Tail block (unused for n % BLOCK == 0, kept for safety)
        const int floats = (remaining > 0 ? remaining : 0) * NSH;
        for (int i = tid; i < floats; i += BLOCK)
            out[base + i] = sh[i];
    }
}

extern "C" void kernel_launch(void* const* d_in, const int* in_sizes, int n_in,
                              void* d_out, int out_size)
{
    const float* alpha = (const float*)d_in[0];
    const float* beta  = (const float*)d_in[1];
    float* out = (float*)d_out;
    const int n = in_sizes[0];
    const int grid = (n + BLOCK - 1) / BLOCK;
    sh_ab_kernel<<<grid, BLOCK>>>(alpha, beta, out, n);
}

// round 4
// speedup vs baseline: 1.1245x; 1.1245x over previous
#include <cuda_runtime.h>
#include <math.h>

#define BLOCK 64
#define NSH 81   // sum(2l+1), l=0..8

// Real spherical harmonics (e3nn SphericalHarmonicsAlphaBeta, l=0..8, mul=1).
// out[n, l*l + l + m] = P̄_{l,|m|}(cos b) * sin(b)^|m| * A_m(a)
//   A_m = 1 (m=0), sqrt(2)*cos(m a) (m>0), sqrt(2)*sin(|m| a) (m<0)
// P̄ via stable fully-normalized ALF recurrences (no Condon-Shortley phase).
// Writeback is fully WARP-LOCAL: each warp stages its 32x81 tile in its own
// smem region and streams it out itself (__syncwarp only, no CTA barrier),
// so resident warps stay phase-decoupled and the store stream stays smooth.
__global__ __launch_bounds__(BLOCK)
void sh_ab_kernel(const float* __restrict__ alpha,
                  const float* __restrict__ beta,
                  float* __restrict__ out, int n)
{
    __shared__ __align__(16) float sh[BLOCK * NSH];   // 20736 B -> 11 CTAs/SM

    const int tid  = threadIdx.x;
    const int wid  = tid >> 5;          // warp in block
    const int lane = tid & 31;
    const int point = blockIdx.x * BLOCK + tid;

    float a = 0.f, b = 0.f;
    if (point < n) { a = alpha[point]; b = beta[point]; }

    float sa, ca, sb, cb;
    __sincosf(a, &sa, &ca);
    __sincosf(b, &sb, &cb);
    const float z = cb;   // polynomial variable
    const float y = sb;   // sin(beta) >= 0 on [0, pi]

    // cos(m a), sin(m a) for m=0..8 via Chebyshev recurrence
    float cm[9], sn[9];
    cm[0] = 1.f; sn[0] = 0.f;
    cm[1] = ca;  sn[1] = sa;
    const float t2 = 2.f * ca;
#pragma unroll
    for (int m = 2; m <= 8; ++m) {
        cm[m] = t2 * cm[m-1] - cm[m-2];
        sn[m] = t2 * sn[m-1] - sn[m-2];
    }

    const float SQ2 = 1.41421356237309515f;
    float* warp_tile = &sh[wid * 32 * NSH];
    float* row = &warp_tile[lane * NSH];

    // m-major sweep: tiny live register set per column
    float pmm = 0.28209479177387814f;   // P̄_00 = sqrt(1/4pi)
#pragma unroll
    for (int m = 0; m <= 8; ++m) {
        if (m > 0)
            pmm *= sqrtf((2.f*m + 1.f) / (2.f*m)) * y;   // sectoral step

        const float Ac = (m == 0) ? 1.f : SQ2 * cm[m];
        const float As = SQ2 * sn[m];

        // l = m
        float plm2 = pmm;
        {
            const int l = m;
            row[l*l + l + m] = plm2 * Ac;
            if (m > 0) row[l*l + l - m] = plm2 * As;
        }
        if (m < 8) {
            // l = m+1
            float plm1 = sqrtf(2.f*m + 3.f) * z * pmm;
            {
                const int l = m + 1;
                row[l*l + l + m] = plm1 * Ac;
                if (m > 0) row[l*l + l - m] = plm1 * As;
            }
            // l = m+2 .. 8
#pragma unroll
            for (int l = m + 2; l <= 8; ++l) {
                const float al = sqrtf((4.f*l*l - 1.f) / (float)(l*l - m*m));
                const float bl = sqrtf((float)((l-1)*(l-1) - m*m) /
                                       (4.f*(l-1)*(l-1) - 1.f));
                const float pl = al * (z * plm1 - bl * plm2);
                row[l*l + l + m] = pl * Ac;
                if (m > 0) row[l*l + l - m] = pl * As;
                plm2 = plm1; plm1 = pl;
            }
        }
    }

    __syncwarp();

    // Warp-local coalesced streaming writeback: 32*81 floats = 648 float4
    const long long warp_base =
        (long long)(blockIdx.x * BLOCK + wid * 32) * NSH;
    const int remaining = n - (blockIdx.x * BLOCK + wid * 32);
    if (remaining >= 32) {
        float4* dst = reinterpret_cast<float4*>(out + warp_base);
        const float4* src = reinterpret_cast<const float4*>(warp_tile);
#pragma unroll 5
        for (int i = lane; i < (32 * NSH) / 4; i += 32)
            __stcs(&dst[i], src[i]);
    } else {
        const int floats = (remaining > 0 ? remaining : 0) * NSH;
        for (int i = lane; i < floats; i += 32)
            __stcs(&out[warp_base + i], warp_tile[i]);
    }
}

extern "C" void kernel_launch(void* const* d_in, const int* in_sizes, int n_in,
                              void* d_out, int out_size)
{
    const float* alpha = (const float*)d_in[0];
    const float* beta  = (const float*)d_in[1];
    float* out = (float*)d_out;
    const int n = in_sizes[0];
    const int grid = (n + BLOCK - 1) / BLOCK;
    sh_ab_kernel<<<grid, BLOCK>>>(alpha, beta, out, n);
}